// round 9
// baseline (speedup 1.0000x reference)
#include <cuda_runtime.h>
#include <math.h>

#define BATCH 8192
#define NSTEP 256

#define K_DT      0.01f
#define K_HDT     0.005f
#define K_DT6     ((float)(0.01/6.0))
#define K_INV_M   (1.0f/0.033f)
#define K_MG      (0.033f*9.81f)
#define K_KT      3.8e-8f
#define K_KTARM   ((float)(3.8e-8*0.04))
#define K_KC      3.8e-11f
#define K_JX      1.4e-5f
#define K_JZ      2.17e-5f
#define K_INV_JX  (1.0f/1.4e-5f)
#define K_INV_JZ  (1.0f/2.17e-5f)

#define F_PI      3.14159265358979f
#define F_PIO2    1.57079632679490f
#define F_PIO4    0.78539816339745f

// ---------- raw MUFU primitives ----------
__device__ __forceinline__ float rcp_raw(float x) {
    float r; asm("rcp.approx.f32 %0, %1;" : "=f"(r) : "f"(x)); return r;
}
__device__ __forceinline__ float sqrt_raw(float x) {
    float r; asm("sqrt.approx.f32 %0, %1;" : "=f"(r) : "f"(x)); return r;
}

// atan2 for y >= 0, 4-term Cephes (err ~1e-8) — feeds the stored so3 output only
__device__ __forceinline__ float atan2_pos_full(float y, float x) {
    float ax = fabsf(x);
    float mn = fminf(y, ax);
    float mx = fmaxf(y, ax);
    float t  = mn * rcp_raw(mx);
    bool big = t > 0.41421356f;
    float tb = (t - 1.0f) * rcp_raw(t + 1.0f);
    float t2 = big ? tb : t;
    float z  = t2 * t2;
    float p  = (((8.05374449538e-2f * z - 1.38776856032e-1f) * z
                 + 1.99777106478e-1f) * z - 3.33329491539e-1f) * z * t2 + t2;
    p = big ? p + F_PIO4 : p;
    p = (y > ax) ? F_PIO2 - p : p;
    p = (x < 0.0f) ? F_PI - p : p;
    return p;
}

// sin/cos of a perturbation — 3-term, good to |d| ~ 1.5 (covers the near-2pi corner)
__device__ __forceinline__ void sincos_delta(float d, float& sd, float& cd) {
    float d2 = d * d;
    sd = d * fmaf(d2, fmaf(d2, fmaf(d2, -1.9841270e-4f, 8.3333333e-3f), -1.6666667e-1f), 1.0f);
    cd = fmaf(d2, fmaf(d2, fmaf(d2, -1.3888889e-3f, 4.1666667e-2f), -0.5f), 1.0f);
}

// ---------- mid-stage roundtrip: exp(log(normalize(a))) ~= Taylor-normalize(a) ----------
// eps-shrink omission here is dt-suppressed in the final state (R8-validated).
__device__ __forceinline__ void roundtrip_mid(float ax, float ay, float az, float aw,
                                              float& qx, float& qy, float& qz, float& qw)
{
    float n2  = fmaf(ax, ax, fmaf(ay, ay, fmaf(az, az, aw * aw)));
    float inv = fmaf(-0.5f, n2, 1.5f);            // Taylor 1/||a||  (||a||^2 = 1+O(1e-4))
    qx = ax * inv;
    qy = ay * inv;
    qz = az * inv;
    qw = aw * inv;
}

// ---------- end-of-step ----------
// Carried q_next: alpha enters ONLY via eps-shrink delta -> crude alpha
// (pi/2)*(1-w): exact at alpha=0 and alpha=pi (where delta is largest), <=15%
// mid-range -> carried-q angle error ~1.5e-7/step. Keeps the atan2 OFF the
// inter-step dependency chain.
// Stored r output: accurate 4-term atan2, computed after q_next (overlappable
// with the next iteration's stage-1 work).
__device__ __forceinline__ void roundtrip_full(float ax, float ay, float az, float aw,
                                               float& qx, float& qy, float& qz, float& qw,
                                               float& rx, float& ry, float& rz)
{
    float nv2 = ax * ax + ay * ay + az * az;
    float n2  = nv2 + aw * aw;
    float inv = fmaf(-0.5f, n2, 1.5f);            // Taylor 1/||a||
    float nvr = sqrt_raw(nv2);
    float rnvr = rcp_raw(fmaxf(nvr, 1e-30f));
    float nv = nvr * inv;
    float w  = aw * inv;
    float rn = rcp_raw(nv + 1e-6f);
    bool tiny = nv < 1e-6f;

    // --- q-path (critical): crude alpha ---
    float alpha_c = fmaf(-F_PIO2, w, F_PIO2);     // (pi/2)*(1-w)
    float delta = -1e-6f * alpha_c * rn;
    float sd, cd;
    sincos_delta(delta, sd, cd);
    float s  = fmaf(nv, cd,  w * sd);             // sin(alpha*g)
    float c  = fmaf(w,  cd, -nv * sd);            // cos(alpha*g)
    float ks = s * rnvr;
    qx = tiny ? ax * inv : ax * ks;
    qy = tiny ? ay * inv : ay * ks;
    qz = tiny ? az * inv : az * ks;
    qw = tiny ? 1.0f     : c;

    // --- r-path (off the carry chain): accurate alpha ---
    float alpha = atan2_pos_full(nvr, aw);
    float klog = tiny ? 2.0f : 2.0f * alpha * rn;
    float ki = klog * inv;
    rx = ki * ax;
    ry = ki * ay;
    rz = ki * az;
}

// full exp for arbitrary-norm so3 (preloop only; theta can exceed pi)
__device__ __forceinline__ void quat_from_so3(float rx, float ry, float rz,
                                              float& qx, float& qy, float& qz, float& qw)
{
    float t2    = rx * rx + ry * ry + rz * rz;
    float theta = sqrtf(t2);
    float s, c;
    sincosf(0.5f * theta, &s, &c);
    float k = s / (theta + 1e-8f);
    bool small = theta < 1e-6f;
    k  = small ? 0.5f : k;
    qw = small ? 1.0f : c;
    qx = k * rx;
    qy = k * ry;
    qz = k * rz;
}

struct Deriv { float ax, ay, az, qdx, qdy, qdz, qdw, wdx, wdy, wdz; };

__device__ __forceinline__ void dyn_stage(float qx, float qy, float qz, float qw,
                                          float wx, float wy, float wz,
                                          float T, float tx, float ty, float tz,
                                          Deriv& d)
{
    float t_x = 2.0f * (qy * T);
    float t_y = -2.0f * (qx * T);
    float twx = qw * t_x - qz * t_y;
    float twy = qw * t_y + qz * t_x;
    float twz = T + (qx * t_y - qy * t_x);
    d.ax = twx * K_INV_M;
    d.ay = twy * K_INV_M;
    d.az = (twz - K_MG) * K_INV_M;

    float Jwx = K_JX * wx, Jwy = K_JX * wy, Jwz = K_JZ * wz;
    float cx = wy * Jwz - wz * Jwy;
    float cy = wz * Jwx - wx * Jwz;
    float cz = wx * Jwy - wy * Jwx;
    d.wdx = (tx - cx) * K_INV_JX;
    d.wdy = (ty - cy) * K_INV_JX;
    d.wdz = (tz - cz) * K_INV_JZ;

    d.qdx = 0.5f * (qw * wx + (qy * wz - qz * wy));
    d.qdy = 0.5f * (qw * wy + (qz * wx - qx * wz));
    d.qdz = 0.5f * (qw * wz + (qx * wy - qy * wx));
    d.qdw = -0.5f * (qx * wx + qy * wy + qz * wz);
}

__global__ void __launch_bounds__(64, 1)
quad_rollout_kernel(const float* __restrict__ x0,
                    const float* __restrict__ u_seq,
                    float* __restrict__ out)
{
    int b = blockIdx.x * blockDim.x + threadIdx.x;
    if (b >= BATCH) return;

    const float4* x04 = reinterpret_cast<const float4*>(x0) + (size_t)b * 3;
    float4 s0 = x04[0];
    float4 s1 = x04[1];
    float4 s2 = x04[2];
    float px = s0.x, py = s0.y, pz = s0.z;
    float vx = s0.w, vy = s1.x, vz = s1.y;
    float wx = s2.y, wy = s2.z, wz = s2.w;

    float qx, qy, qz, qw;
    quat_from_so3(s1.z, s1.w, s2.x, qx, qy, qz, qw);

    const float4* u4 = reinterpret_cast<const float4*>(u_seq) + (size_t)b * NSTEP;
    float4* o4 = reinterpret_cast<float4*>(out) + (size_t)b * NSTEP * 3;

    float4 um = u4[0];

#pragma unroll 1
    for (int t = 0; t < NSTEP; ++t) {
        float4 unext = u4[(t + 1 < NSTEP) ? (t + 1) : t];

        // motor_to_phys; clips never bind for u in [0,1); /MAX*MAX round-trip dropped (~1ulp of 5e-7-scale term)
        float m0 = um.x * um.x, m1 = um.y * um.y, m2 = um.z * um.z, m3 = um.w * um.w;
        float T  = K_KT * ((m0 + m1) + (m2 + m3));
        float tx = K_KTARM * ((m2 + m3) - (m0 + m1));
        float ty = K_KTARM * ((m1 + m2) - (m0 + m3));
        float tz = K_KC * ((m0 + m2) - (m1 + m3));

        // ---- stage 1 ----
        Deriv d1;
        dyn_stage(qx, qy, qz, qw, wx, wy, wz, T, tx, ty, tz, d1);

        // ---- stage 2 ----
        float q2x, q2y, q2z, q2w;
        roundtrip_mid(qx + K_HDT * d1.qdx, qy + K_HDT * d1.qdy,
                      qz + K_HDT * d1.qdz, qw + K_HDT * d1.qdw,
                      q2x, q2y, q2z, q2w);
        Deriv d2;
        dyn_stage(q2x, q2y, q2z, q2w,
                  wx + K_HDT * d1.wdx, wy + K_HDT * d1.wdy, wz + K_HDT * d1.wdz,
                  T, tx, ty, tz, d2);

        // ---- stage 3 ----
        float q3x, q3y, q3z, q3w;
        roundtrip_mid(qx + K_HDT * d2.qdx, qy + K_HDT * d2.qdy,
                      qz + K_HDT * d2.qdz, qw + K_HDT * d2.qdw,
                      q3x, q3y, q3z, q3w);
        Deriv d3;
        dyn_stage(q3x, q3y, q3z, q3w,
                  wx + K_HDT * d2.wdx, wy + K_HDT * d2.wdy, wz + K_HDT * d2.wdz,
                  T, tx, ty, tz, d3);

        // ---- stage 4 ----
        float q4x, q4y, q4z, q4w;
        roundtrip_mid(qx + K_DT * d3.qdx, qy + K_DT * d3.qdy,
                      qz + K_DT * d3.qdz, qw + K_DT * d3.qdw,
                      q4x, q4y, q4z, q4w);
        Deriv d4;
        dyn_stage(q4x, q4y, q4z, q4w,
                  wx + K_DT * d3.wdx, wy + K_DT * d3.wdy, wz + K_DT * d3.wdz,
                  T, tx, ty, tz, d4);

        // ---- next-step quat first (critical path) ----
        float anx = qx + K_DT6 * (((d1.qdx + 2.0f * d2.qdx) + 2.0f * d3.qdx) + d4.qdx);
        float any_ = qy + K_DT6 * (((d1.qdy + 2.0f * d2.qdy) + 2.0f * d3.qdy) + d4.qdy);
        float anz = qz + K_DT6 * (((d1.qdz + 2.0f * d2.qdz) + 2.0f * d3.qdz) + d4.qdz);
        float anw = qw + K_DT6 * (((d1.qdw + 2.0f * d2.qdw) + 2.0f * d3.qdw) + d4.qdw);
        float rox, roy, roz;
        roundtrip_full(anx, any_, anz, anw, qx, qy, qz, qw, rox, roy, roz);

        // ---- pos/vel/omega combine (off the inter-step dependency chain) ----
        float v2x = vx + K_HDT * d1.ax, v2y = vy + K_HDT * d1.ay, v2z = vz + K_HDT * d1.az;
        float v3x = vx + K_HDT * d2.ax, v3y = vy + K_HDT * d2.ay, v3z = vz + K_HDT * d2.az;
        float v4x = vx + K_DT  * d3.ax, v4y = vy + K_DT  * d3.ay, v4z = vz + K_DT  * d3.az;

        px = px + K_DT6 * (((vx + 2.0f * v2x) + 2.0f * v3x) + v4x);
        py = py + K_DT6 * (((vy + 2.0f * v2y) + 2.0f * v3y) + v4y);
        pz = pz + K_DT6 * (((vz + 2.0f * v2z) + 2.0f * v3z) + v4z);

        vx = vx + K_DT6 * (((d1.ax + 2.0f * d2.ax) + 2.0f * d3.ax) + d4.ax);
        vy = vy + K_DT6 * (((d1.ay + 2.0f * d2.ay) + 2.0f * d3.ay) + d4.ay);
        vz = vz + K_DT6 * (((d1.az + 2.0f * d2.az) + 2.0f * d3.az) + d4.az);

        wx = wx + K_DT6 * (((d1.wdx + 2.0f * d2.wdx) + 2.0f * d3.wdx) + d4.wdx);
        wy = wy + K_DT6 * (((d1.wdy + 2.0f * d2.wdy) + 2.0f * d3.wdy) + d4.wdy);
        wz = wz + K_DT6 * (((d1.wdz + 2.0f * d2.wdz) + 2.0f * d3.wdz) + d4.wdz);

        o4[t * 3 + 0] = make_float4(px, py, pz, vx);
        o4[t * 3 + 1] = make_float4(vy, vz, rox, roy);
        o4[t * 3 + 2] = make_float4(roz, wx, wy, wz);

        um = unext;
    }
}

extern "C" void kernel_launch(void* const* d_in, const int* in_sizes, int n_in,
                              void* d_out, int out_size)
{
    const float* x0 = (const float*)d_in[0];
    const float* us = (const float*)d_in[1];
    if (n_in >= 2 && in_sizes[0] != BATCH * 12) {
        const float* tmp = x0; x0 = us; us = tmp;
    }
    float* out = (float*)d_out;

    dim3 block(64);
    dim3 grid(BATCH / 64);
    quad_rollout_kernel<<<grid, block>>>(x0, us, out);
}

// round 11
// speedup vs baseline: 1.0439x; 1.0439x over previous
#include <cuda_runtime.h>
#include <math.h>

#define BATCH 8192
#define NSTEP 256

#define K_DT      0.01f
#define K_HDT     0.005f
#define K_DT6     ((float)(0.01/6.0))
#define K_INV_M   (1.0f/0.033f)
#define K_MG      (0.033f*9.81f)
#define K_KT      3.8e-8f
#define K_KTARM   ((float)(3.8e-8*0.04))
#define K_KC      3.8e-11f
#define K_JX      1.4e-5f
#define K_JZ      2.17e-5f
#define K_INV_JX  (1.0f/1.4e-5f)
#define K_INV_JZ  (1.0f/2.17e-5f)

#define F_PI      3.14159265358979f
#define F_PIO2    1.57079632679490f
#define F_PIO4    0.78539816339745f

// ---------- raw MUFU primitives ----------
__device__ __forceinline__ float rcp_raw(float x) {
    float r; asm("rcp.approx.f32 %0, %1;" : "=f"(r) : "f"(x)); return r;
}
__device__ __forceinline__ float sqrt_raw(float x) {
    float r; asm("sqrt.approx.f32 %0, %1;" : "=f"(r) : "f"(x)); return r;
}

// atan2 for y >= 0, 4-term Cephes (err ~1e-8)
__device__ __forceinline__ float atan2_pos_full(float y, float x) {
    float ax = fabsf(x);
    float mn = fminf(y, ax);
    float mx = fmaxf(y, ax);
    float t  = mn * rcp_raw(mx);
    bool big = t > 0.41421356f;
    float tb = (t - 1.0f) * rcp_raw(t + 1.0f);
    float t2 = big ? tb : t;
    float z  = t2 * t2;
    float p  = (((8.05374449538e-2f * z - 1.38776856032e-1f) * z
                 + 1.99777106478e-1f) * z - 3.33329491539e-1f) * z * t2 + t2;
    p = big ? p + F_PIO4 : p;
    p = (y > ax) ? F_PIO2 - p : p;
    p = (x < 0.0f) ? F_PI - p : p;
    return p;
}

// sin/cos of a perturbation — 3-term, good to |d| ~ 1.5 (covers the near-2pi corner)
__device__ __forceinline__ void sincos_delta(float d, float& sd, float& cd) {
    float d2 = d * d;
    sd = d * fmaf(d2, fmaf(d2, fmaf(d2, -1.9841270e-4f, 8.3333333e-3f), -1.6666667e-1f), 1.0f);
    cd = fmaf(d2, fmaf(d2, fmaf(d2, -1.3888889e-3f, 4.1666667e-2f), -0.5f), 1.0f);
}

// ---------- end-of-step: r = log(normalize(a)) (output) AND q_next = exp(r) ----------
// (R8 form: accurate alpha on both paths)
__device__ __forceinline__ void roundtrip_full(float ax, float ay, float az, float aw,
                                               float& qx, float& qy, float& qz, float& qw,
                                               float& rx, float& ry, float& rz)
{
    float nv2 = ax * ax + ay * ay + az * az;
    float n2  = nv2 + aw * aw;
    float inv = fmaf(-0.5f, n2, 1.5f);            // Taylor 1/||a||  (||a||^2 = 1+O(1e-4))
    float nvr = sqrt_raw(nv2);
    float rnvr = rcp_raw(fmaxf(nvr, 1e-30f));
    float alpha = atan2_pos_full(nvr, aw);
    float nv = nvr * inv;
    float w  = aw * inv;
    float rn = rcp_raw(nv + 1e-6f);
    float delta = -1e-6f * alpha * rn;
    float sd, cd;
    sincos_delta(delta, sd, cd);
    float s  = fmaf(nv, cd,  w * sd);
    float c  = fmaf(w,  cd, -nv * sd);
    float ks = s * rnvr;
    bool tiny = nv < 1e-6f;
    qx = tiny ? ax * inv : ax * ks;
    qy = tiny ? ay * inv : ay * ks;
    qz = tiny ? az * inv : az * ks;
    qw = tiny ? 1.0f     : c;

    float klog = tiny ? 2.0f : 2.0f * alpha * rn;
    float ki = klog * inv;
    rx = ki * ax;
    ry = ki * ay;
    rz = ki * az;
}

// full exp for arbitrary-norm so3 (preloop only; theta can exceed pi)
__device__ __forceinline__ void quat_from_so3(float rx, float ry, float rz,
                                              float& qx, float& qy, float& qz, float& qw)
{
    float t2    = rx * rx + ry * ry + rz * rz;
    float theta = sqrtf(t2);
    float s, c;
    sincosf(0.5f * theta, &s, &c);
    float k = s / (theta + 1e-8f);
    bool small = theta < 1e-6f;
    k  = small ? 0.5f : k;
    qw = small ? 1.0f : c;
    qx = k * rx;
    qy = k * ry;
    qz = k * rz;
}

struct Deriv { float ax, ay, az, qdx, qdy, qdz, qdw, wdx, wdy, wdz; };

// NOTE: tolerant of slightly non-unit q (||q||^2 = 1+O(1e-4)):
// thrust error O(1e-4)*T with T ~ 1e-7*mg -> pos/vel immune; qd scale error
// O(1e-4) is wiped by the end-of-step normalize (direction error ~1e-8/step).
__device__ __forceinline__ void dyn_stage(float qx, float qy, float qz, float qw,
                                          float wx, float wy, float wz,
                                          float T, float tx, float ty, float tz,
                                          Deriv& d)
{
    float t_x = 2.0f * (qy * T);
    float t_y = -2.0f * (qx * T);
    float twx = qw * t_x - qz * t_y;
    float twy = qw * t_y + qz * t_x;
    float twz = T + (qx * t_y - qy * t_x);
    d.ax = twx * K_INV_M;
    d.ay = twy * K_INV_M;
    d.az = (twz - K_MG) * K_INV_M;

    float Jwx = K_JX * wx, Jwy = K_JX * wy, Jwz = K_JZ * wz;
    float cx = wy * Jwz - wz * Jwy;
    float cy = wz * Jwx - wx * Jwz;
    float cz = wx * Jwy - wy * Jwx;
    d.wdx = (tx - cx) * K_INV_JX;
    d.wdy = (ty - cy) * K_INV_JX;
    d.wdz = (tz - cz) * K_INV_JZ;

    d.qdx = 0.5f * (qw * wx + (qy * wz - qz * wy));
    d.qdy = 0.5f * (qw * wy + (qz * wx - qx * wz));
    d.qdz = 0.5f * (qw * wz + (qx * wy - qy * wx));
    d.qdw = -0.5f * (qx * wx + qy * wy + qz * wz);
}

__global__ void __launch_bounds__(64, 1)
quad_rollout_kernel(const float* __restrict__ x0,
                    const float* __restrict__ u_seq,
                    float* __restrict__ out)
{
    int b = blockIdx.x * blockDim.x + threadIdx.x;
    if (b >= BATCH) return;

    const float4* x04 = reinterpret_cast<const float4*>(x0) + (size_t)b * 3;
    float4 s0 = x04[0];
    float4 s1 = x04[1];
    float4 s2 = x04[2];
    float px = s0.x, py = s0.y, pz = s0.z;
    float vx = s0.w, vy = s1.x, vz = s1.y;
    float wx = s2.y, wy = s2.z, wz = s2.w;

    float qx, qy, qz, qw;
    quat_from_so3(s1.z, s1.w, s2.x, qx, qy, qz, qw);

    const float4* u4 = reinterpret_cast<const float4*>(u_seq) + (size_t)b * NSTEP;
    float4* o4 = reinterpret_cast<float4*>(out) + (size_t)b * NSTEP * 3;

    float4 um = u4[0];

#pragma unroll 1
    for (int t = 0; t < NSTEP; ++t) {
        float4 unext = u4[(t + 1 < NSTEP) ? (t + 1) : t];

        // motor_to_phys; clips never bind for u in [0,1); /MAX*MAX round-trip dropped (~1ulp of 5e-7-scale term)
        float m0 = um.x * um.x, m1 = um.y * um.y, m2 = um.z * um.z, m3 = um.w * um.w;
        float T  = K_KT * ((m0 + m1) + (m2 + m3));
        float tx = K_KTARM * ((m2 + m3) - (m0 + m1));
        float ty = K_KTARM * ((m1 + m2) - (m0 + m3));
        float tz = K_KC * ((m0 + m2) - (m1 + m3));

        // ---- stage 1 ----
        Deriv d1;
        dyn_stage(qx, qy, qz, qw, wx, wy, wz, T, tx, ty, tz, d1);

        // ---- stage 2 (mid-stage quats unnormalized: ||q||^2 = 1+O(1e-4), see dyn_stage note) ----
        Deriv d2;
        dyn_stage(qx + K_HDT * d1.qdx, qy + K_HDT * d1.qdy,
                  qz + K_HDT * d1.qdz, qw + K_HDT * d1.qdw,
                  wx + K_HDT * d1.wdx, wy + K_HDT * d1.wdy, wz + K_HDT * d1.wdz,
                  T, tx, ty, tz, d2);

        // ---- stage 3 ----
        Deriv d3;
        dyn_stage(qx + K_HDT * d2.qdx, qy + K_HDT * d2.qdy,
                  qz + K_HDT * d2.qdz, qw + K_HDT * d2.qdw,
                  wx + K_HDT * d2.wdx, wy + K_HDT * d2.wdy, wz + K_HDT * d2.wdz,
                  T, tx, ty, tz, d3);

        // ---- stage 4 ----
        Deriv d4;
        dyn_stage(qx + K_DT * d3.qdx, qy + K_DT * d3.qdy,
                  qz + K_DT * d3.qdz, qw + K_DT * d3.qdw,
                  wx + K_DT * d3.wdx, wy + K_DT * d3.wdy, wz + K_DT * d3.wdz,
                  T, tx, ty, tz, d4);

        // ---- next-step quat first (critical path) ----
        float anx = qx + K_DT6 * (((d1.qdx + 2.0f * d2.qdx) + 2.0f * d3.qdx) + d4.qdx);
        float any_ = qy + K_DT6 * (((d1.qdy + 2.0f * d2.qdy) + 2.0f * d3.qdy) + d4.qdy);
        float anz = qz + K_DT6 * (((d1.qdz + 2.0f * d2.qdz) + 2.0f * d3.qdz) + d4.qdz);
        float anw = qw + K_DT6 * (((d1.qdw + 2.0f * d2.qdw) + 2.0f * d3.qdw) + d4.qdw);
        float rox, roy, roz;
        roundtrip_full(anx, any_, anz, anw, qx, qy, qz, qw, rox, roy, roz);

        // ---- pos/vel/omega combine (off the inter-step dependency chain) ----
        float v2x = vx + K_HDT * d1.ax, v2y = vy + K_HDT * d1.ay, v2z = vz + K_HDT * d1.az;
        float v3x = vx + K_HDT * d2.ax, v3y = vy + K_HDT * d2.ay, v3z = vz + K_HDT * d2.az;
        float v4x = vx + K_DT  * d3.ax, v4y = vy + K_DT  * d3.ay, v4z = vz + K_DT  * d3.az;

        px = px + K_DT6 * (((vx + 2.0f * v2x) + 2.0f * v3x) + v4x);
        py = py + K_DT6 * (((vy + 2.0f * v2y) + 2.0f * v3y) + v4y);
        pz = pz + K_DT6 * (((vz + 2.0f * v2z) + 2.0f * v3z) + v4z);

        vx = vx + K_DT6 * (((d1.ax + 2.0f * d2.ax) + 2.0f * d3.ax) + d4.ax);
        vy = vy + K_DT6 * (((d1.ay + 2.0f * d2.ay) + 2.0f * d3.ay) + d4.ay);
        vz = vz + K_DT6 * (((d1.az + 2.0f * d2.az) + 2.0f * d3.az) + d4.az);

        wx = wx + K_DT6 * (((d1.wdx + 2.0f * d2.wdx) + 2.0f * d3.wdx) + d4.wdx);
        wy = wy + K_DT6 * (((d1.wdy + 2.0f * d2.wdy) + 2.0f * d3.wdy) + d4.wdy);
        wz = wz + K_DT6 * (((d1.wdz + 2.0f * d2.wdz) + 2.0f * d3.wdz) + d4.wdz);

        o4[t * 3 + 0] = make_float4(px, py, pz, vx);
        o4[t * 3 + 1] = make_float4(vy, vz, rox, roy);
        o4[t * 3 + 2] = make_float4(roz, wx, wy, wz);

        um = unext;
    }
}

extern "C" void kernel_launch(void* const* d_in, const int* in_sizes, int n_in,
                              void* d_out, int out_size)
{
    const float* x0 = (const float*)d_in[0];
    const float* us = (const float*)d_in[1];
    if (n_in >= 2 && in_sizes[0] != BATCH * 12) {
        const float* tmp = x0; x0 = us; us = tmp;
    }
    float* out = (float*)d_out;

    dim3 block(64);
    dim3 grid(BATCH / 64);
    quad_rollout_kernel<<<grid, block>>>(x0, us, out);
}

// round 12
// speedup vs baseline: 1.0636x; 1.0189x over previous
#include <cuda_runtime.h>
#include <math.h>

#define BATCH 8192
#define NSTEP 256

#define K_DT      0.01f
#define K_HDT     0.005f
#define K_DT6     ((float)(0.01/6.0))
#define K_DT22    (0.5f * K_DT * K_DT)         /* dt^2/2 = 5e-5 */
#define K_INV_M   (1.0f/0.033f)
#define K_MG      (0.033f*9.81f)
#define K_KT      3.8e-8f
#define K_KTARM   ((float)(3.8e-8*0.04))
#define K_KC      3.8e-11f
#define K_JX      1.4e-5f
#define K_JZ      2.17e-5f
#define K_INV_JX  (1.0f/1.4e-5f)
#define K_INV_JZ  (1.0f/2.17e-5f)

#define F_PI      3.14159265358979f
#define F_PIO2    1.57079632679490f
#define F_PIO4    0.78539816339745f

// ---------- raw MUFU primitives ----------
__device__ __forceinline__ float rcp_raw(float x) {
    float r; asm("rcp.approx.f32 %0, %1;" : "=f"(r) : "f"(x)); return r;
}
__device__ __forceinline__ float sqrt_raw(float x) {
    float r; asm("sqrt.approx.f32 %0, %1;" : "=f"(r) : "f"(x)); return r;
}

// atan2 for y >= 0, 4-term Cephes (err ~1e-8)
__device__ __forceinline__ float atan2_pos_full(float y, float x) {
    float ax = fabsf(x);
    float mn = fminf(y, ax);
    float mx = fmaxf(y, ax);
    float t  = mn * rcp_raw(mx);
    bool big = t > 0.41421356f;
    float tb = (t - 1.0f) * rcp_raw(t + 1.0f);
    float t2 = big ? tb : t;
    float z  = t2 * t2;
    float p  = (((8.05374449538e-2f * z - 1.38776856032e-1f) * z
                 + 1.99777106478e-1f) * z - 3.33329491539e-1f) * z * t2 + t2;
    p = big ? p + F_PIO4 : p;
    p = (y > ax) ? F_PIO2 - p : p;
    p = (x < 0.0f) ? F_PI - p : p;
    return p;
}

// sin/cos of a perturbation — 3-term, good to |d| ~ 1.5 (covers the near-2pi corner)
__device__ __forceinline__ void sincos_delta(float d, float& sd, float& cd) {
    float d2 = d * d;
    sd = d * fmaf(d2, fmaf(d2, fmaf(d2, -1.9841270e-4f, 8.3333333e-3f), -1.6666667e-1f), 1.0f);
    cd = fmaf(d2, fmaf(d2, fmaf(d2, -1.3888889e-3f, 4.1666667e-2f), -0.5f), 1.0f);
}

// ---------- end-of-step: r = log(normalize(a)) (output) AND q_next = exp(r) ----------
__device__ __forceinline__ void roundtrip_full(float ax, float ay, float az, float aw,
                                               float& qx, float& qy, float& qz, float& qw,
                                               float& rx, float& ry, float& rz)
{
    float nv2 = ax * ax + ay * ay + az * az;
    float n2  = nv2 + aw * aw;
    float inv = fmaf(-0.5f, n2, 1.5f);            // Taylor 1/||a||  (||a||^2 = 1+O(1e-4))
    float nvr = sqrt_raw(nv2);
    float rnvr = rcp_raw(fmaxf(nvr, 1e-30f));
    float alpha = atan2_pos_full(nvr, aw);
    float nv = nvr * inv;
    float w  = aw * inv;
    float rn = rcp_raw(nv + 1e-6f);
    float delta = -1e-6f * alpha * rn;
    float sd, cd;
    sincos_delta(delta, sd, cd);
    float s  = fmaf(nv, cd,  w * sd);
    float c  = fmaf(w,  cd, -nv * sd);
    float ks = s * rnvr;
    bool tiny = nv < 1e-6f;
    qx = tiny ? ax * inv : ax * ks;
    qy = tiny ? ay * inv : ay * ks;
    qz = tiny ? az * inv : az * ks;
    qw = tiny ? 1.0f     : c;

    float klog = tiny ? 2.0f : 2.0f * alpha * rn;
    float ki = klog * inv;
    rx = ki * ax;
    ry = ki * ay;
    rz = ki * az;
}

// full exp for arbitrary-norm so3 (preloop only; theta can exceed pi)
__device__ __forceinline__ void quat_from_so3(float rx, float ry, float rz,
                                              float& qx, float& qy, float& qz, float& qw)
{
    float t2    = rx * rx + ry * ry + rz * rz;
    float theta = sqrtf(t2);
    float s, c;
    sincosf(0.5f * theta, &s, &c);
    float k = s / (theta + 1e-8f);
    bool small = theta < 1e-6f;
    k  = small ? 0.5f : k;
    qw = small ? 1.0f : c;
    qx = k * rx;
    qy = k * ry;
    qz = k * rz;
}

struct DerivR { float qdx, qdy, qdz, qdw, wdx, wdy, wdz; };  // rotation-channel derivs only

// Rotation-channel derivatives. Tolerant of slightly non-unit q (R11-validated).
__device__ __forceinline__ void dyn_rot(float qx, float qy, float qz, float qw,
                                        float wx, float wy, float wz,
                                        float tx, float ty, float tz,
                                        DerivR& d)
{
    float Jwx = K_JX * wx, Jwy = K_JX * wy, Jwz = K_JZ * wz;
    float cx = wy * Jwz - wz * Jwy;
    float cy = wz * Jwx - wx * Jwz;
    float cz = wx * Jwy - wy * Jwx;
    d.wdx = (tx - cx) * K_INV_JX;
    d.wdy = (ty - cy) * K_INV_JX;
    d.wdz = (tz - cz) * K_INV_JZ;

    d.qdx = 0.5f * (qw * wx + (qy * wz - qz * wy));
    d.qdy = 0.5f * (qw * wy + (qz * wx - qx * wz));
    d.qdz = 0.5f * (qw * wz + (qx * wy - qy * wx));
    d.qdw = -0.5f * (qx * wx + qy * wy + qz * wz);
}

__global__ void __launch_bounds__(64, 1)
quad_rollout_kernel(const float* __restrict__ x0,
                    const float* __restrict__ u_seq,
                    float* __restrict__ out)
{
    int b = blockIdx.x * blockDim.x + threadIdx.x;
    if (b >= BATCH) return;

    const float4* x04 = reinterpret_cast<const float4*>(x0) + (size_t)b * 3;
    float4 s0 = x04[0];
    float4 s1 = x04[1];
    float4 s2 = x04[2];
    float px = s0.x, py = s0.y, pz = s0.z;
    float vx = s0.w, vy = s1.x, vz = s1.y;
    float wx = s2.y, wy = s2.z, wz = s2.w;

    float qx, qy, qz, qw;
    quat_from_so3(s1.z, s1.w, s2.x, qx, qy, qz, qw);

    const float4* u4 = reinterpret_cast<const float4*>(u_seq) + (size_t)b * NSTEP;
    float4* o4 = reinterpret_cast<float4*>(out) + (size_t)b * NSTEP * 3;

    float4 um = u4[0];

#pragma unroll 1
    for (int t = 0; t < NSTEP; ++t) {
        float4 unext = u4[(t + 1 < NSTEP) ? (t + 1) : t];

        // motor_to_phys; clips never bind for u in [0,1); /MAX*MAX round-trip dropped
        float m0 = um.x * um.x, m1 = um.y * um.y, m2 = um.z * um.z, m3 = um.w * um.w;
        float T  = K_KT * ((m0 + m1) + (m2 + m3));
        float tx = K_KTARM * ((m2 + m3) - (m0 + m1));
        float ty = K_KTARM * ((m1 + m2) - (m0 + m3));
        float tz = K_KC * ((m0 + m2) - (m1 + m3));

        // ---- acceleration ONCE per step (thrust/g ~ 2e-7: stage-to-stage acc
        // differences ~5e-8 m/s^2 -> ~1e-7 absolute on final vel/pos; RK4 vel
        // combine then collapses exactly to v += dt*a, pos += dt*v + dt^2/2*a) ----
        float t_x = 2.0f * (qy * T);
        float t_y = -2.0f * (qx * T);
        float ax_ = (qw * t_x - qz * t_y) * K_INV_M;
        float ay_ = (qw * t_y + qz * t_x) * K_INV_M;
        float az_ = (T + (qx * t_y - qy * t_x) - K_MG) * K_INV_M;

        // ---- stage 1 ----
        DerivR d1;
        dyn_rot(qx, qy, qz, qw, wx, wy, wz, tx, ty, tz, d1);

        // ---- stage 2 (mid-stage quats unnormalized, R11-validated) ----
        DerivR d2;
        dyn_rot(qx + K_HDT * d1.qdx, qy + K_HDT * d1.qdy,
                qz + K_HDT * d1.qdz, qw + K_HDT * d1.qdw,
                wx + K_HDT * d1.wdx, wy + K_HDT * d1.wdy, wz + K_HDT * d1.wdz,
                tx, ty, tz, d2);

        // ---- stage 3 ----
        DerivR d3;
        dyn_rot(qx + K_HDT * d2.qdx, qy + K_HDT * d2.qdy,
                qz + K_HDT * d2.qdz, qw + K_HDT * d2.qdw,
                wx + K_HDT * d2.wdx, wy + K_HDT * d2.wdy, wz + K_HDT * d2.wdz,
                tx, ty, tz, d3);

        // ---- stage 4 ----
        DerivR d4;
        dyn_rot(qx + K_DT * d3.qdx, qy + K_DT * d3.qdy,
                qz + K_DT * d3.qdz, qw + K_DT * d3.qdw,
                wx + K_DT * d3.wdx, wy + K_DT * d3.wdy, wz + K_DT * d3.wdz,
                tx, ty, tz, d4);

        // ---- next-step quat first (critical path) ----
        float anx = qx + K_DT6 * (((d1.qdx + 2.0f * d2.qdx) + 2.0f * d3.qdx) + d4.qdx);
        float any_ = qy + K_DT6 * (((d1.qdy + 2.0f * d2.qdy) + 2.0f * d3.qdy) + d4.qdy);
        float anz = qz + K_DT6 * (((d1.qdz + 2.0f * d2.qdz) + 2.0f * d3.qdz) + d4.qdz);
        float anw = qw + K_DT6 * (((d1.qdw + 2.0f * d2.qdw) + 2.0f * d3.qdw) + d4.qdw);
        float rox, roy, roz;
        roundtrip_full(anx, any_, anz, anw, qx, qy, qz, qw, rox, roy, roz);

        // ---- pos/vel (collapsed combines; off the inter-step chain) ----
        px = px + K_DT * vx + K_DT22 * ax_;
        py = py + K_DT * vy + K_DT22 * ay_;
        pz = pz + K_DT * vz + K_DT22 * az_;

        vx = vx + K_DT * ax_;
        vy = vy + K_DT * ay_;
        vz = vz + K_DT * az_;

        wx = wx + K_DT6 * (((d1.wdx + 2.0f * d2.wdx) + 2.0f * d3.wdx) + d4.wdx);
        wy = wy + K_DT6 * (((d1.wdy + 2.0f * d2.wdy) + 2.0f * d3.wdy) + d4.wdy);
        wz = wz + K_DT6 * (((d1.wdz + 2.0f * d2.wdz) + 2.0f * d3.wdz) + d4.wdz);

        o4[t * 3 + 0] = make_float4(px, py, pz, vx);
        o4[t * 3 + 1] = make_float4(vy, vz, rox, roy);
        o4[t * 3 + 2] = make_float4(roz, wx, wy, wz);

        um = unext;
    }
}

extern "C" void kernel_launch(void* const* d_in, const int* in_sizes, int n_in,
                              void* d_out, int out_size)
{
    const float* x0 = (const float*)d_in[0];
    const float* us = (const float*)d_in[1];
    if (n_in >= 2 && in_sizes[0] != BATCH * 12) {
        const float* tmp = x0; x0 = us; us = tmp;
    }
    float* out = (float*)d_out;

    dim3 block(64);
    dim3 grid(BATCH / 64);
    quad_rollout_kernel<<<grid, block>>>(x0, us, out);
}

// round 15
// speedup vs baseline: 1.0805x; 1.0159x over previous
#include <cuda_runtime.h>
#include <math.h>

#define BATCH 8192
#define NSTEP 256

#define K_DT      0.01f
#define K_HDT     0.005f
#define K_A2      0.0025f                      /* HDT*0.5, exact */
#define K_DT6     ((float)(0.01/6.0))
#define K_DT12    (K_DT6 * 0.5f)               /* exact halving */
#define K_DT22    (0.5f * K_DT * K_DT)
#define K_INV_M   (1.0f/0.033f)
#define K_MG      (0.033f*9.81f)
#define K_KT      3.8e-8f
#define K_KTARM   ((float)(3.8e-8*0.04))
#define K_KC      3.8e-11f
#define K_JX      1.4e-5f
#define K_JZ      2.17e-5f
#define K_INV_JX  (1.0f/1.4e-5f)
#define K_INV_JZ  (1.0f/2.17e-5f)
#define K_C1      ((K_JX - K_JZ) * K_INV_JX)   /* (Jy-Jz)/Jx = -0.55 */
#define K_C2      ((K_JZ - K_JX) * K_INV_JX)   /* (Jz-Jx)/Jy = +0.55 */

#define F_PI      3.14159265358979f
#define F_PIO2    1.57079632679490f
#define F_PIO4    0.78539816339745f

// ---------- raw MUFU primitives ----------
__device__ __forceinline__ float rcp_raw(float x) {
    float r; asm("rcp.approx.f32 %0, %1;" : "=f"(r) : "f"(x)); return r;
}
__device__ __forceinline__ float sqrt_raw(float x) {
    float r; asm("sqrt.approx.f32 %0, %1;" : "=f"(r) : "f"(x)); return r;
}

// atan2 for y >= 0, 4-term Cephes (err ~1e-8)
__device__ __forceinline__ float atan2_pos_full(float y, float x) {
    float ax = fabsf(x);
    float mn = fminf(y, ax);
    float mx = fmaxf(y, ax);
    float t  = mn * rcp_raw(mx);
    bool big = t > 0.41421356f;
    float tb = (t - 1.0f) * rcp_raw(t + 1.0f);
    float t2 = big ? tb : t;
    float z  = t2 * t2;
    float p  = (((8.05374449538e-2f * z - 1.38776856032e-1f) * z
                 + 1.99777106478e-1f) * z - 3.33329491539e-1f) * z * t2 + t2;
    p = big ? p + F_PIO4 : p;
    p = (y > ax) ? F_PIO2 - p : p;
    p = (x < 0.0f) ? F_PI - p : p;
    return p;
}

// sin/cos of a perturbation — 3-term, good to |d| ~ 1.5 (covers the near-2pi corner)
__device__ __forceinline__ void sincos_delta(float d, float& sd, float& cd) {
    float d2 = d * d;
    sd = d * fmaf(d2, fmaf(d2, fmaf(d2, -1.9841270e-4f, 8.3333333e-3f), -1.6666667e-1f), 1.0f);
    cd = fmaf(d2, fmaf(d2, fmaf(d2, -1.3888889e-3f, 4.1666667e-2f), -0.5f), 1.0f);
}

// ---------- end-of-step: r = log(normalize(a)) (output) AND q_next = exp(r) ----------
__device__ __forceinline__ void roundtrip_full(float ax, float ay, float az, float aw,
                                               float& qx, float& qy, float& qz, float& qw,
                                               float& rx, float& ry, float& rz)
{
    float nv2 = ax * ax + ay * ay + az * az;
    float n2  = nv2 + aw * aw;
    float inv = fmaf(-0.5f, n2, 1.5f);            // Taylor 1/||a||  (||a||^2 = 1+O(1e-4))
    float nvr = sqrt_raw(nv2);
    float rnvr = rcp_raw(fmaxf(nvr, 1e-30f));
    float alpha = atan2_pos_full(nvr, aw);
    float nv = nvr * inv;
    float w  = aw * inv;
    float rn = rcp_raw(nv + 1e-6f);
    float delta = -1e-6f * alpha * rn;
    float sd, cd;
    sincos_delta(delta, sd, cd);
    float s  = fmaf(nv, cd,  w * sd);
    float c  = fmaf(w,  cd, -nv * sd);
    float ks = s * rnvr;
    bool tiny = nv < 1e-6f;
    qx = tiny ? ax * inv : ax * ks;
    qy = tiny ? ay * inv : ay * ks;
    qz = tiny ? az * inv : az * ks;
    qw = tiny ? 1.0f     : c;

    float klog = tiny ? 2.0f : 2.0f * alpha * rn;
    float ki = klog * inv;
    rx = ki * ax;
    ry = ki * ay;
    rz = ki * az;
}

// full exp for arbitrary-norm so3 (preloop only; theta can exceed pi)
__device__ __forceinline__ void quat_from_so3(float rx, float ry, float rz,
                                              float& qx, float& qy, float& qz, float& qw)
{
    float t2    = rx * rx + ry * ry + rz * rz;
    float theta = sqrtf(t2);
    float s, c;
    sincosf(0.5f * theta, &s, &c);
    float k = s / (theta + 1e-8f);
    bool small = theta < 1e-6f;
    k  = small ? 0.5f : k;
    qw = small ? 1.0f : c;
    qx = k * rx;
    qy = k * ry;
    qz = k * rz;
}

struct DerivR { float ex, ey, ez, ew, wdx, wdy; };  // e = 2*qd; wdz = tzJ (per-step const)

// Rotation-channel derivatives, Jx==Jy exploited:
//   (omega x J omega)_z == 0 exactly -> wdz = tz/Jz (caller holds it)
//   wdx = fma(wy*wz, (Jy-Jz)/Jx, txJ); wdy = fma(wz*wx, (Jz-Jx)/Jy, tyJ)
// e = 2*quat_derivative (0.5 folded into step constants; bit-exact).
// Tolerant of slightly non-unit q (R11-validated).
__device__ __forceinline__ void dyn_rot(float qx, float qy, float qz, float qw,
                                        float wx, float wy, float wz,
                                        float txJ, float tyJ,
                                        DerivR& d)
{
    d.wdx = fmaf(wy * wz, K_C1, txJ);
    d.wdy = fmaf(wz * wx, K_C2, tyJ);

    d.ex = fmaf(qw, wx, fmaf(qy, wz, -(qz * wy)));
    d.ey = fmaf(qw, wy, fmaf(qz, wx, -(qx * wz)));
    d.ez = fmaf(qw, wz, fmaf(qx, wy, -(qy * wx)));
    d.ew = -fmaf(qx, wx, fmaf(qy, wy, qz * wz));
}

__global__ void __launch_bounds__(64, 1)
quad_rollout_kernel(const float* __restrict__ x0,
                    const float* __restrict__ u_seq,
                    float* __restrict__ out)
{
    int b = blockIdx.x * blockDim.x + threadIdx.x;
    if (b >= BATCH) return;

    const float4* x04 = reinterpret_cast<const float4*>(x0) + (size_t)b * 3;
    float4 s0 = x04[0];
    float4 s1 = x04[1];
    float4 s2 = x04[2];
    float px = s0.x, py = s0.y, pz = s0.z;
    float vx = s0.w, vy = s1.x, vz = s1.y;
    float wx = s2.y, wy = s2.z, wz = s2.w;

    float qx, qy, qz, qw;
    quat_from_so3(s1.z, s1.w, s2.x, qx, qy, qz, qw);

    const float4* u4 = reinterpret_cast<const float4*>(u_seq) + (size_t)b * NSTEP;
    float4* o4 = reinterpret_cast<float4*>(out) + (size_t)b * NSTEP * 3;

    float4 um = u4[0];

#pragma unroll 1
    for (int t = 0; t < NSTEP; ++t) {
        float4 unext = u4[(t + 1 < NSTEP) ? (t + 1) : t];

        // motor_to_phys; clips never bind for u in [0,1); /MAX*MAX round-trip dropped
        float m0 = um.x * um.x, m1 = um.y * um.y, m2 = um.z * um.z, m3 = um.w * um.w;
        float T   = K_KT * ((m0 + m1) + (m2 + m3));
        float txJ = (K_KTARM * K_INV_JX) * ((m2 + m3) - (m0 + m1));
        float tyJ = (K_KTARM * K_INV_JX) * ((m1 + m2) - (m0 + m3));
        float tzJ = (K_KC * K_INV_JZ) * ((m0 + m2) - (m1 + m3));

        // ---- acceleration once per step (thrust/g ~ 2e-7; R12-validated) ----
        float t_x = 2.0f * (qy * T);
        float t_y = -2.0f * (qx * T);
        float ax_ = (qw * t_x - qz * t_y) * K_INV_M;
        float ay_ = (qw * t_y + qz * t_x) * K_INV_M;
        float az_ = (T + (qx * t_y - qy * t_x) - K_MG) * K_INV_M;

        // omega-z stage values (wdz = tzJ at every stage)
        float w2z = fmaf(K_HDT, tzJ, wz);
        float w4z = fmaf(K_DT,  tzJ, wz);

        // ---- stage 1 ----
        DerivR d1;
        dyn_rot(qx, qy, qz, qw, wx, wy, wz, txJ, tyJ, d1);

        // ---- stage 2 (mid-stage quats unnormalized, R11-validated) ----
        DerivR d2;
        dyn_rot(fmaf(K_A2, d1.ex, qx), fmaf(K_A2, d1.ey, qy),
                fmaf(K_A2, d1.ez, qz), fmaf(K_A2, d1.ew, qw),
                fmaf(K_HDT, d1.wdx, wx), fmaf(K_HDT, d1.wdy, wy), w2z,
                txJ, tyJ, d2);

        // ---- stage 3 ----
        DerivR d3;
        dyn_rot(fmaf(K_A2, d2.ex, qx), fmaf(K_A2, d2.ey, qy),
                fmaf(K_A2, d2.ez, qz), fmaf(K_A2, d2.ew, qw),
                fmaf(K_HDT, d2.wdx, wx), fmaf(K_HDT, d2.wdy, wy), w2z,
                txJ, tyJ, d3);

        // ---- stage 4 (DT*0.5 = HDT exact) ----
        DerivR d4;
        dyn_rot(fmaf(K_HDT, d3.ex, qx), fmaf(K_HDT, d3.ey, qy),
                fmaf(K_HDT, d3.ez, qz), fmaf(K_HDT, d3.ew, qw),
                fmaf(K_DT, d3.wdx, wx), fmaf(K_DT, d3.wdy, wy), w4z,
                txJ, tyJ, d4);

        // ---- next-step quat first (critical path) ----
        float esx = fmaf(2.0f, d3.ex, fmaf(2.0f, d2.ex, d1.ex)) + d4.ex;
        float esy = fmaf(2.0f, d3.ey, fmaf(2.0f, d2.ey, d1.ey)) + d4.ey;
        float esz = fmaf(2.0f, d3.ez, fmaf(2.0f, d2.ez, d1.ez)) + d4.ez;
        float esw = fmaf(2.0f, d3.ew, fmaf(2.0f, d2.ew, d1.ew)) + d4.ew;
        float rox, roy, roz;
        roundtrip_full(fmaf(K_DT12, esx, qx), fmaf(K_DT12, esy, qy),
                       fmaf(K_DT12, esz, qz), fmaf(K_DT12, esw, qw),
                       qx, qy, qz, qw, rox, roy, roz);

        // ---- pos/vel (collapsed combines; off the inter-step chain) ----
        px = px + K_DT * vx + K_DT22 * ax_;
        py = py + K_DT * vy + K_DT22 * ay_;
        pz = pz + K_DT * vz + K_DT22 * az_;

        vx = vx + K_DT * ax_;
        vy = vy + K_DT * ay_;
        vz = vz + K_DT * az_;

        wx = wx + K_DT6 * (fmaf(2.0f, d3.wdx, fmaf(2.0f, d2.wdx, d1.wdx)) + d4.wdx);
        wy = wy + K_DT6 * (fmaf(2.0f, d3.wdy, fmaf(2.0f, d2.wdy, d1.wdy)) + d4.wdy);
        wz = fmaf(K_DT, tzJ, wz);

        o4[t * 3 + 0] = make_float4(px, py, pz, vx);
        o4[t * 3 + 1] = make_float4(vy, vz, rox, roy);
        o4[t * 3 + 2] = make_float4(roz, wx, wy, wz);

        um = unext;
    }
}

extern "C" void kernel_launch(void* const* d_in, const int* in_sizes, int n_in,
                              void* d_out, int out_size)
{
    const float* x0 = (const float*)d_in[0];
    const float* us = (const float*)d_in[1];
    if (n_in >= 2 && in_sizes[0] != BATCH * 12) {
        const float* tmp = x0; x0 = us; us = tmp;
    }
    float* out = (float*)d_out;

    dim3 block(64);
    dim3 grid(BATCH / 64);
    quad_rollout_kernel<<<grid, block>>>(x0, us, out);
}